// round 13
// baseline (speedup 1.0000x reference)
#include <cuda_runtime.h>
#include <cuda_bf16.h>
#include <cuda_fp16.h>
#include <mma.h>
#include <cstdint>

using namespace nvcuda;

#define NNODES 50000
#define NPAD   50048      // padded rows so tile stores never go OOB
#define RREL   4
#define EDGES  80000
#define NGEMM  5          // slot 0 = self-loop, 1..4 = relations

// ---------------------------------------------------------------------------
// Static device scratch. Device code references symbols directly (R2 lesson:
// host-shadow addresses silently read host memory via ATS on GB300).
// ---------------------------------------------------------------------------
__device__ float  g_Hacc[(size_t)NPAD * 256];          // self-loop + accumulator (fp32, 51 MB)
__device__ __half g_Hf[(size_t)RREL * NPAD * 256];     // relation outputs (fp16, 102 MB)
__device__ int    g_deg[RREL * NNODES];
__device__ float  g_invdeg[RREL * NNODES];
__device__ __half g_x_h[(size_t)NNODES * 256];         // fp16 copy of x
__device__ __half g_w_h[NGEMM * 256 * 256];            // [g][n][k] (W transposed)

// ---------------------------------------------------------------------------
// degree pipeline
// ---------------------------------------------------------------------------
__global__ void zero_deg_kernel() {
    int i = blockIdx.x * blockDim.x + threadIdx.x;
    if (i < RREL * NNODES) g_deg[i] = 0;
}
__global__ void deg_kernel(const int* __restrict__ dst) {
    int i = blockIdx.x * blockDim.x + threadIdx.x;
    if (i < RREL * EDGES) {
        int r = i / EDGES;
        atomicAdd(&g_deg[r * NNODES + dst[i]], 1);
    }
}
__global__ void invdeg_kernel() {
    int i = blockIdx.x * blockDim.x + threadIdx.x;
    if (i < RREL * NNODES)
        g_invdeg[i] = 1.0f / fmaxf((float)g_deg[i], 1.0f);
}

// ---------------------------------------------------------------------------
// Prep: cast x to fp16 (shared A operand of all 5 GEMMs)
// ---------------------------------------------------------------------------
__global__ void convert_x_kernel(const float* __restrict__ x) {
    size_t total = (size_t)NNODES * 64;   // float4 count
    for (size_t i = (size_t)blockIdx.x * blockDim.x + threadIdx.x; i < total;
         i += (size_t)gridDim.x * blockDim.x) {
        float4 v = reinterpret_cast<const float4*>(x)[i];
        __half2 h01 = __float22half2_rn(make_float2(v.x, v.y));
        __half2 h23 = __float22half2_rn(make_float2(v.z, v.w));
        reinterpret_cast<__half2*>(g_x_h)[2 * i]     = h01;
        reinterpret_cast<__half2*>(g_x_h)[2 * i + 1] = h23;
    }
}

// Prep: transpose+cast weights into B layout W_t[g][n][k] = W_g[k][n]
__global__ void convert_w_kernel(const float* __restrict__ weight,
                                 const float* __restrict__ wself) {
    int i = blockIdx.x * blockDim.x + threadIdx.x;
    if (i >= NGEMM * 65536) return;
    int g = i >> 16;
    int n = (i >> 8) & 255;
    int k = i & 255;
    const float* src = (g == 0) ? wself : weight + (size_t)(g - 1) * 65536;
    g_w_h[i] = __float2half_rn(src[k * 256 + n]);
}

// ---------------------------------------------------------------------------
// fp16 wmma GEMM, cp.async double-buffered, warp tile 64x64.
// g=0: fp32 store to g_Hacc. g>0: fp16 store to g_Hf[g-1] (via smem staging).
// grid (391, 2, 5), 128 threads (4 warps, 2x2). Block tile 128x128, KC=32.
// Dynamic smem: max(pipeline 40960, staging 65536) = 65536 B.
// ---------------------------------------------------------------------------
#define KC   32
#define LDS  40                   // row stride (halves); 80 B
#define TILE_ELEMS (128 * LDS)    // 5120

__device__ __forceinline__ uint32_t smem_u32(const void* p) {
    uint32_t a;
    asm("{ .reg .u64 t; cvta.to.shared.u64 t, %1; cvt.u32.u64 %0, t; }" : "=r"(a) : "l"(p));
    return a;
}
__device__ __forceinline__ void cpa16(uint32_t dst, const void* src) {
    asm volatile("cp.async.cg.shared.global [%0], [%1], 16;" :: "r"(dst), "l"(src));
}
__device__ __forceinline__ void cpa16_zfill(uint32_t dst, const void* src) {
    asm volatile("cp.async.cg.shared.global [%0], [%1], 16, 0;" :: "r"(dst), "l"(src));
}

__global__ void __launch_bounds__(128)
wmma_gemm_kernel() {
    extern __shared__ __half smem[];

    const int tid  = threadIdx.x;
    const int wid  = tid >> 5;
    const int lane = tid & 31;
    const int wm   = wid & 1;          // warp rows wm*64..+63
    const int wn   = wid >> 1;         // warp cols wn*64..+63
    const int m0   = blockIdx.x * 128;
    const int n0   = blockIdx.y * 128;
    const int g    = blockIdx.z;

    const __half* wh = g_w_h + (size_t)g * 65536;

    // per-thread load coords: 512 uint4 per matrix tile, 4 per thread
    const int lrow0 = tid >> 2;                 // 0..31
    const int lc4   = tid & 3;                  // uint4 slot in 32-wide k row

    auto issue_tile = [&](int t) {
        const int k0 = t * KC;
        const int stage = t & 1;
        __half* As = smem + (stage * 2 + 0) * TILE_ELEMS;
        __half* Bs = smem + (stage * 2 + 1) * TILE_ELEMS;
        #pragma unroll
        for (int p = 0; p < 4; p++) {
            int row = lrow0 + p * 32;
            int kof = k0 + lc4 * 8;
            uint32_t soff = (uint32_t)(row * LDS + lc4 * 8) * 2;  // bytes
            int gm = m0 + row;
            if (gm < NNODES) {
                cpa16(smem_u32(As) + soff, g_x_h + (size_t)gm * 256 + kof);
            } else {
                cpa16_zfill(smem_u32(As) + soff, g_x_h);
            }
            int n = n0 + row;
            cpa16(smem_u32(Bs) + soff, wh + (size_t)n * 256 + kof);
        }
        asm volatile("cp.async.commit_group;" ::: "memory");
    };

    wmma::fragment<wmma::accumulator, 16, 16, 16, float> c[4][4];
    #pragma unroll
    for (int mi = 0; mi < 4; mi++)
        #pragma unroll
        for (int ni = 0; ni < 4; ni++)
            wmma::fill_fragment(c[mi][ni], 0.0f);

    issue_tile(0);

    for (int t = 0; t < 8; t++) {
        if (t + 1 < 8) {
            issue_tile(t + 1);
            asm volatile("cp.async.wait_group 1;" ::: "memory");
        } else {
            asm volatile("cp.async.wait_group 0;" ::: "memory");
        }
        __syncthreads();   // stage t data visible to all warps

        const int stage = t & 1;
        const __half* As = smem + (stage * 2 + 0) * TILE_ELEMS;
        const __half* Bs = smem + (stage * 2 + 1) * TILE_ELEMS;

        #pragma unroll
        for (int ks = 0; ks < 2; ks++) {
            const int kk = ks * 16;
            wmma::fragment<wmma::matrix_a, 16, 16, 16, __half, wmma::row_major> a[4];
            wmma::fragment<wmma::matrix_b, 16, 16, 16, __half, wmma::col_major> b[4];
            #pragma unroll
            for (int mi = 0; mi < 4; mi++)
                wmma::load_matrix_sync(a[mi], As + (wm * 64 + mi * 16) * LDS + kk, LDS);
            #pragma unroll
            for (int ni = 0; ni < 4; ni++)
                wmma::load_matrix_sync(b[ni], Bs + (wn * 64 + ni * 16) * LDS + kk, LDS);
            #pragma unroll
            for (int mi = 0; mi < 4; mi++)
                #pragma unroll
                for (int ni = 0; ni < 4; ni++)
                    wmma::mma_sync(c[mi][ni], a[mi], b[ni], c[mi][ni]);
        }
        __syncthreads();   // all warps done with stage t before it is reloaded
    }

    if (g == 0) {
        // fp32 store to the accumulator buffer (rows < NPAD always in-bounds)
        #pragma unroll
        for (int mi = 0; mi < 4; mi++)
            #pragma unroll
            for (int ni = 0; ni < 4; ni++) {
                int row = m0 + wm * 64 + mi * 16;
                int col = n0 + wn * 64 + ni * 16;
                wmma::store_matrix_sync(g_Hacc + (size_t)row * 256 + col, c[mi][ni],
                                        256, wmma::mem_row_major);
            }
    } else {
        // fp16 store: stage each warp's 64x64 fp32 tile in smem, convert, write.
        // smem is free (final __syncthreads above); each warp owns 16 KB.
        float* stage = reinterpret_cast<float*>(smem) + wid * 4096;
        #pragma unroll
        for (int mi = 0; mi < 4; mi++)
            #pragma unroll
            for (int ni = 0; ni < 4; ni++)
                wmma::store_matrix_sync(stage + (mi * 16) * 64 + ni * 16, c[mi][ni],
                                        64, wmma::mem_row_major);
        // store_matrix_sync is warp-synchronous; same-warp readback is safe.
        __half* Hg = g_Hf + (size_t)(g - 1) * NPAD * 256;
        const float2* st2 = reinterpret_cast<const float2*>(stage);
        #pragma unroll
        for (int e = 0; e < 64; e++) {          // 2048 half2 / 32 lanes
            int idx = e * 32 + lane;
            int row = idx >> 5;                  // 0..63
            int c2  = idx & 31;                  // half2 column
            float2 f = st2[row * 32 + c2];
            __half2 h = __float22half2_rn(f);
            int grow = m0 + wm * 64 + row;
            reinterpret_cast<__half2*>(Hg + (size_t)grow * 256 + n0 + wn * 64)[c2] = h;
        }
    }
}

// ---------------------------------------------------------------------------
// Scatter ALL relations: Hacc[d] += invdeg[r][d] * Hf[r][s]  (one warp/edge)
// Each lane reads one uint4 = 8 halves, converts, scales, 2x red.v4.f32.
// ---------------------------------------------------------------------------
__global__ void scatter_all_kernel(const int* __restrict__ src,
                                   const int* __restrict__ dst) {
    int gw   = (blockIdx.x * blockDim.x + threadIdx.x) >> 5;
    int lane = threadIdx.x & 31;
    if (gw >= RREL * EDGES) return;
    int r = gw / EDGES;
    int s = src[gw];
    int d = dst[gw];
    float w = g_invdeg[r * NNODES + d];

    const __half* h = g_Hf + ((size_t)r * NPAD + s) * 256 + lane * 8;
    uint4 hv = *reinterpret_cast<const uint4*>(h);
    const __half2* hp = reinterpret_cast<const __half2*>(&hv);
    float2 f0 = __half22float2(hp[0]);
    float2 f1 = __half22float2(hp[1]);
    float2 f2 = __half22float2(hp[2]);
    float2 f3 = __half22float2(hp[3]);

    float* a = g_Hacc + (size_t)d * 256 + lane * 8;
    asm volatile("red.global.add.v4.f32 [%0], {%1,%2,%3,%4};"
                 :: "l"(a), "f"(f0.x * w), "f"(f0.y * w), "f"(f1.x * w), "f"(f1.y * w)
                 : "memory");
    asm volatile("red.global.add.v4.f32 [%0], {%1,%2,%3,%4};"
                 :: "l"(a + 4), "f"(f2.x * w), "f"(f2.y * w), "f"(f3.x * w), "f"(f3.y * w)
                 : "memory");
}

// ---------------------------------------------------------------------------
// Epilogue: out = relu(Hacc + bias)
// ---------------------------------------------------------------------------
__global__ void epilogue_kernel(const float* __restrict__ bias,
                                float* __restrict__ out) {
    size_t i = (size_t)blockIdx.x * blockDim.x + threadIdx.x;
    size_t total4 = (size_t)NNODES * 64;
    if (i < total4) {
        float4 v = reinterpret_cast<const float4*>(g_Hacc)[i];
        int c = (int)(i & 63) * 4;
        v.x = fmaxf(v.x + bias[c + 0], 0.f);
        v.y = fmaxf(v.y + bias[c + 1], 0.f);
        v.z = fmaxf(v.z + bias[c + 2], 0.f);
        v.w = fmaxf(v.w + bias[c + 3], 0.f);
        reinterpret_cast<float4*>(out)[i] = v;
    }
}

// ---------------------------------------------------------------------------
extern "C" void kernel_launch(void* const* d_in, const int* in_sizes, int n_in,
                              void* d_out, int out_size) {
    const float* x      = (const float*)d_in[0];
    const int*   src    = (const int*)  d_in[1];
    const int*   dst    = (const int*)  d_in[2];
    const float* weight = (const float*)d_in[3];
    const float* wself  = (const float*)d_in[4];
    const float* bias   = (const float*)d_in[5];
    float* out = (float*)d_out;

    const int SMEM_BYTES = 65536;   // max(pipeline 40960, staging 4*16384)
    cudaFuncSetAttribute(wmma_gemm_kernel,
                         cudaFuncAttributeMaxDynamicSharedMemorySize, SMEM_BYTES);

    // Launch order keeps wmma_gemm at captured-profile index 3.
    convert_x_kernel<<<2048, 256>>>(x);                                   // 0
    convert_w_kernel<<<(NGEMM * 65536 + 255) / 256, 256>>>(weight, wself);// 1
    zero_deg_kernel<<<(RREL * NNODES + 255) / 256, 256>>>();              // 2
    wmma_gemm_kernel<<<dim3(391, 2, NGEMM), 128, SMEM_BYTES>>>();         // 3
    deg_kernel<<<(RREL * EDGES + 255) / 256, 256>>>(dst);                 // 4
    invdeg_kernel<<<(RREL * NNODES + 255) / 256, 256>>>();                // 5

    int sblocks = (RREL * EDGES * 32 + 255) / 256;   // 40000
    scatter_all_kernel<<<sblocks, 256>>>(src, dst);                       // 6

    epilogue_kernel<<<(NNODES * 64 + 255) / 256, 256>>>(bias, out);       // 7
}

// round 14
// speedup vs baseline: 1.1413x; 1.1413x over previous
#include <cuda_runtime.h>
#include <cuda_bf16.h>
#include <cuda_fp16.h>
#include <mma.h>
#include <cstdint>

using namespace nvcuda;

#define NNODES 50000
#define NPAD   50048      // padded rows so store_matrix_sync never goes OOB
#define RREL   4
#define EDGES  80000
#define NGEMM  5          // slot 0 = self-loop, 1..4 = relations

// ---------------------------------------------------------------------------
// Static device scratch. Device code references symbols directly (R2 lesson:
// host-shadow addresses silently read host memory via ATS on GB300).
// ---------------------------------------------------------------------------
__device__ float  g_Hp[(size_t)NGEMM * NPAD * 256];    // 256.2 MB
__device__ int    g_deg[RREL * NNODES];
__device__ float  g_invdeg[RREL * NNODES];
__device__ __half g_x_h[(size_t)NNODES * 256];         // fp16 copy of x
__device__ __half g_w_h[NGEMM * 256 * 256];            // [g][n][k] (W transposed)

// ---------------------------------------------------------------------------
// degree pipeline
// ---------------------------------------------------------------------------
__global__ void zero_deg_kernel() {
    int i = blockIdx.x * blockDim.x + threadIdx.x;
    if (i < RREL * NNODES) g_deg[i] = 0;
}
__global__ void deg_kernel(const int* __restrict__ dst) {
    int i = blockIdx.x * blockDim.x + threadIdx.x;
    if (i < RREL * EDGES) {
        int r = i / EDGES;
        atomicAdd(&g_deg[r * NNODES + dst[i]], 1);
    }
}
__global__ void invdeg_kernel() {
    int i = blockIdx.x * blockDim.x + threadIdx.x;
    if (i < RREL * NNODES)
        g_invdeg[i] = 1.0f / fmaxf((float)g_deg[i], 1.0f);
}

// ---------------------------------------------------------------------------
// Prep: cast x to fp16 (shared A operand of all 5 GEMMs)
// ---------------------------------------------------------------------------
__global__ void convert_x_kernel(const float* __restrict__ x) {
    size_t total = (size_t)NNODES * 64;   // float4 count
    for (size_t i = (size_t)blockIdx.x * blockDim.x + threadIdx.x; i < total;
         i += (size_t)gridDim.x * blockDim.x) {
        float4 v = reinterpret_cast<const float4*>(x)[i];
        __half2 h01 = __float22half2_rn(make_float2(v.x, v.y));
        __half2 h23 = __float22half2_rn(make_float2(v.z, v.w));
        reinterpret_cast<__half2*>(g_x_h)[2 * i]     = h01;
        reinterpret_cast<__half2*>(g_x_h)[2 * i + 1] = h23;
    }
}

// Prep: transpose+cast weights into B layout W_t[g][n][k] = W_g[k][n]
__global__ void convert_w_kernel(const float* __restrict__ weight,
                                 const float* __restrict__ wself) {
    int i = blockIdx.x * blockDim.x + threadIdx.x;
    if (i >= NGEMM * 65536) return;
    int g = i >> 16;
    int n = (i >> 8) & 255;
    int k = i & 255;
    const float* src = (g == 0) ? wself : weight + (size_t)(g - 1) * 65536;
    g_w_h[i] = __float2half_rn(src[k * 256 + n]);
}

// ---------------------------------------------------------------------------
// fp16 wmma GEMM, 3-stage cp.async pipeline, ONE __syncthreads per k-chunk.
// g_Hp[g][:, n0:n0+128] = x_h @ W_h^T   (single term, fp32 accumulate)
// grid (391, 2, 5), 128 threads (4 warps, 2x2). Block tile 128x128, KC=32.
// Dynamic smem: 3 stages x 2 matrices x [128][LDS] half = 61440 B -> 3 CTAs/SM.
// ---------------------------------------------------------------------------
#define KC   32
#define LDS  40                   // row stride (halves); 80 B
#define TILE_ELEMS (128 * LDS)    // 5120
#define NSTAGE 3

__device__ __forceinline__ uint32_t smem_u32(const void* p) {
    uint32_t a;
    asm("{ .reg .u64 t; cvta.to.shared.u64 t, %1; cvt.u32.u64 %0, t; }" : "=r"(a) : "l"(p));
    return a;
}
__device__ __forceinline__ void cpa16(uint32_t dst, const void* src) {
    asm volatile("cp.async.cg.shared.global [%0], [%1], 16;" :: "r"(dst), "l"(src));
}
__device__ __forceinline__ void cpa16_zfill(uint32_t dst, const void* src) {
    asm volatile("cp.async.cg.shared.global [%0], [%1], 16, 0;" :: "r"(dst), "l"(src));
}

__global__ void __launch_bounds__(128)
wmma_gemm_kernel() {
    extern __shared__ __half smem[];

    const int tid = threadIdx.x;
    const int wid = tid >> 5;
    const int wm  = wid & 1;          // warp rows wm*64..+63
    const int wn  = wid >> 1;         // warp cols wn*64..+63
    const int m0  = blockIdx.x * 128;
    const int n0  = blockIdx.y * 128;
    const int g   = blockIdx.z;

    const __half* wh = g_w_h + (size_t)g * 65536;

    // per-thread load coords: 512 uint4 per matrix tile, 4 per thread
    const int lrow0 = tid >> 2;                 // 0..31
    const int lc4   = tid & 3;                  // uint4 slot in 32-wide k row

    auto issue_tile = [&](int t) {
        const int k0 = t * KC;
        const int stage = t % NSTAGE;
        __half* As = smem + (stage * 2 + 0) * TILE_ELEMS;
        __half* Bs = smem + (stage * 2 + 1) * TILE_ELEMS;
        #pragma unroll
        for (int p = 0; p < 4; p++) {
            int row = lrow0 + p * 32;
            int kof = k0 + lc4 * 8;
            uint32_t soff = (uint32_t)(row * LDS + lc4 * 8) * 2;  // bytes
            int gm = m0 + row;
            if (gm < NNODES) {
                cpa16(smem_u32(As) + soff, g_x_h + (size_t)gm * 256 + kof);
            } else {
                cpa16_zfill(smem_u32(As) + soff, g_x_h);
            }
            int n = n0 + row;
            cpa16(smem_u32(Bs) + soff, wh + (size_t)n * 256 + kof);
        }
        asm volatile("cp.async.commit_group;" ::: "memory");
    };

    wmma::fragment<wmma::accumulator, 16, 16, 16, float> c[4][4];
    #pragma unroll
    for (int mi = 0; mi < 4; mi++)
        #pragma unroll
        for (int ni = 0; ni < 4; ni++)
            wmma::fill_fragment(c[mi][ni], 0.0f);

    // prologue: 2 stages in flight
    issue_tile(0);
    issue_tile(1);
    __syncthreads();   // pairs with per-iteration sync pattern below

    for (int t = 0; t < 8; t++) {
        // complete stage t (pending after wait: at most 1 newer group)
        if (t < 7) {
            asm volatile("cp.async.wait_group 1;" ::: "memory");
        } else {
            asm volatile("cp.async.wait_group 0;" ::: "memory");
        }
        __syncthreads();   // stage t visible to all warps

        const int stage = t % NSTAGE;
        const __half* As = smem + (stage * 2 + 0) * TILE_ELEMS;
        const __half* Bs = smem + (stage * 2 + 1) * TILE_ELEMS;

        #pragma unroll
        for (int ks = 0; ks < 2; ks++) {
            const int kk = ks * 16;
            wmma::fragment<wmma::matrix_a, 16, 16, 16, __half, wmma::row_major> a[4];
            wmma::fragment<wmma::matrix_b, 16, 16, 16, __half, wmma::col_major> b[4];
            #pragma unroll
            for (int mi = 0; mi < 4; mi++)
                wmma::load_matrix_sync(a[mi], As + (wm * 64 + mi * 16) * LDS + kk, LDS);
            #pragma unroll
            for (int ni = 0; ni < 4; ni++)
                wmma::load_matrix_sync(b[ni], Bs + (wn * 64 + ni * 16) * LDS + kk, LDS);
            #pragma unroll
            for (int mi = 0; mi < 4; mi++)
                #pragma unroll
                for (int ni = 0; ni < 4; ni++)
                    wmma::mma_sync(c[mi][ni], a[mi], b[ni], c[mi][ni]);
        }

        // Issue the next stage AFTER compute. It writes slot (t+2)%3 ==
        // (t-1)%3, which every warp finished reading in compute(t-1) —
        // strictly before the sync at the top of THIS iteration. No race,
        // and only one barrier per k-chunk.
        if (t + 2 < 8) issue_tile(t + 2);
    }

    // store into padded H (rows < 50048 always in-bounds)
    float* Cg = g_Hp + (size_t)g * NPAD * 256;
    #pragma unroll
    for (int mi = 0; mi < 4; mi++)
        #pragma unroll
        for (int ni = 0; ni < 4; ni++) {
            int row = m0 + wm * 64 + mi * 16;
            int col = n0 + wn * 64 + ni * 16;
            wmma::store_matrix_sync(Cg + (size_t)row * 256 + col, c[mi][ni],
                                    256, wmma::mem_row_major);
        }
}

// ---------------------------------------------------------------------------
// Scatter ALL relations in one launch: Hp[0][d] += invdeg[r][d] * Hp[r+1][s]
// (one warp per edge; Hp[0] already holds the self-loop term)
// ---------------------------------------------------------------------------
__global__ void scatter_all_kernel(const int* __restrict__ src,
                                   const int* __restrict__ dst) {
    int gw   = (blockIdx.x * blockDim.x + threadIdx.x) >> 5;
    int lane = threadIdx.x & 31;
    if (gw >= RREL * EDGES) return;
    int r = gw / EDGES;
    int s = src[gw];
    int d = dst[gw];
    float w = g_invdeg[r * NNODES + d];

    const float4* h = reinterpret_cast<const float4*>(
        g_Hp + ((size_t)(r + 1) * NPAD + s) * 256);
    float* ob = g_Hp + (size_t)d * 256;     // accumulate into Hp[0]
    #pragma unroll
    for (int i = 0; i < 2; i++) {
        float4 v = __ldg(&h[lane + i * 32]);
        v.x *= w; v.y *= w; v.z *= w; v.w *= w;
        float* a = ob + (size_t)(lane + i * 32) * 4;
        asm volatile("red.global.add.v4.f32 [%0], {%1,%2,%3,%4};"
                     :: "l"(a), "f"(v.x), "f"(v.y), "f"(v.z), "f"(v.w) : "memory");
    }
}

// ---------------------------------------------------------------------------
// Epilogue: out = relu(Hp[0] + bias)
// ---------------------------------------------------------------------------
__global__ void epilogue_kernel(const float* __restrict__ bias,
                                float* __restrict__ out) {
    size_t i = (size_t)blockIdx.x * blockDim.x + threadIdx.x;
    size_t total4 = (size_t)NNODES * 64;
    if (i < total4) {
        float4 v = reinterpret_cast<const float4*>(g_Hp)[i];
        int c = (int)(i & 63) * 4;
        v.x = fmaxf(v.x + bias[c + 0], 0.f);
        v.y = fmaxf(v.y + bias[c + 1], 0.f);
        v.z = fmaxf(v.z + bias[c + 2], 0.f);
        v.w = fmaxf(v.w + bias[c + 3], 0.f);
        reinterpret_cast<float4*>(out)[i] = v;
    }
}

// ---------------------------------------------------------------------------
extern "C" void kernel_launch(void* const* d_in, const int* in_sizes, int n_in,
                              void* d_out, int out_size) {
    const float* x      = (const float*)d_in[0];
    const int*   src    = (const int*)  d_in[1];
    const int*   dst    = (const int*)  d_in[2];
    const float* weight = (const float*)d_in[3];
    const float* wself  = (const float*)d_in[4];
    const float* bias   = (const float*)d_in[5];
    float* out = (float*)d_out;

    const int SMEM_BYTES = NSTAGE * 2 * TILE_ELEMS * 2;   // 61440
    cudaFuncSetAttribute(wmma_gemm_kernel,
                         cudaFuncAttributeMaxDynamicSharedMemorySize, SMEM_BYTES);

    // Launch order keeps wmma_gemm at captured-profile index 3.
    convert_x_kernel<<<2048, 256>>>(x);                                   // 0
    convert_w_kernel<<<(NGEMM * 65536 + 255) / 256, 256>>>(weight, wself);// 1
    zero_deg_kernel<<<(RREL * NNODES + 255) / 256, 256>>>();              // 2
    wmma_gemm_kernel<<<dim3(391, 2, NGEMM), 128, SMEM_BYTES>>>();         // 3
    deg_kernel<<<(RREL * EDGES + 255) / 256, 256>>>(dst);                 // 4
    invdeg_kernel<<<(RREL * NNODES + 255) / 256, 256>>>();                // 5

    int sblocks = (RREL * EDGES * 32 + 255) / 256;   // 40000
    scatter_all_kernel<<<sblocks, 256>>>(src, dst);                       // 6

    epilogue_kernel<<<(NNODES * 64 + 255) / 256, 256>>>(bias, out);       // 7
}

// round 15
// speedup vs baseline: 1.1602x; 1.0166x over previous
#include <cuda_runtime.h>
#include <cuda_bf16.h>
#include <cuda_fp16.h>
#include <mma.h>
#include <cstdint>

using namespace nvcuda;

#define NNODES 50000
#define NPAD   50048
#define RREL   4
#define EDGES  80000
#define NGEMM  5          // slot 0 = self-loop, 1..4 = relations
#define SCAN_N (RREL * NNODES)          // 200000
#define SCAN_BLOCKS ((SCAN_N + 255) / 256)   // 782

// ---------------------------------------------------------------------------
// Static device scratch. Device code references symbols directly (R2 lesson:
// host-shadow addresses silently read host memory via ATS on GB300).
// ---------------------------------------------------------------------------
__device__ float  g_Hp[(size_t)NGEMM * NPAD * 256];    // 256.2 MB
__device__ int    g_deg[SCAN_N];
__device__ int    g_off[SCAN_N];        // CSR row offsets (exclusive prefix)
__device__ int    g_cursor[SCAN_N];     // fill cursors
__device__ int    g_bsum[1024];         // block partial sums for the scan
__device__ int    g_esrc[RREL * EDGES]; // CSR edge sources
__device__ __half g_x_h[(size_t)NNODES * 256];
__device__ __half g_w_h[NGEMM * 256 * 256];            // [g][n][k] (W transposed)

// ---------------------------------------------------------------------------
// degree + CSR pipeline
// ---------------------------------------------------------------------------
__global__ void zero_deg_kernel() {
    int i = blockIdx.x * blockDim.x + threadIdx.x;
    if (i < SCAN_N) g_deg[i] = 0;
}
__global__ void deg_kernel(const int* __restrict__ dst) {
    int i = blockIdx.x * blockDim.x + threadIdx.x;
    if (i < RREL * EDGES) {
        int r = i / EDGES;
        atomicAdd(&g_deg[r * NNODES + dst[i]], 1);
    }
}

// scan1: per-block (256 elems) sums -> g_bsum
__global__ void scan1_kernel() {
    __shared__ int ts[256];
    int i = blockIdx.x * 256 + threadIdx.x;
    int v = (i < SCAN_N) ? g_deg[i] : 0;
    ts[threadIdx.x] = v;
    __syncthreads();
    for (int s = 128; s > 0; s >>= 1) {
        if (threadIdx.x < s) ts[threadIdx.x] += ts[threadIdx.x + s];
        __syncthreads();
    }
    if (threadIdx.x == 0) g_bsum[blockIdx.x] = ts[0];
}

// scan2: single block, exclusive scan of the 782 block sums (in place)
__global__ void scan2_kernel() {
    __shared__ int ts[1024];
    int tid = threadIdx.x;
    int v = (tid < SCAN_BLOCKS) ? g_bsum[tid] : 0;
    ts[tid] = v;
    __syncthreads();
    for (int s = 1; s < 1024; s <<= 1) {
        int t = (tid >= s) ? ts[tid - s] : 0;
        __syncthreads();
        ts[tid] += t;
        __syncthreads();
    }
    if (tid < SCAN_BLOCKS) g_bsum[tid] = ts[tid] - v;   // exclusive
}

// scan3: block-local exclusive scan + block base -> g_off, g_cursor
__global__ void scan3_kernel() {
    __shared__ int ts[256];
    int i = blockIdx.x * 256 + threadIdx.x;
    int v = (i < SCAN_N) ? g_deg[i] : 0;
    ts[threadIdx.x] = v;
    __syncthreads();
    for (int s = 1; s < 256; s <<= 1) {
        int t = (threadIdx.x >= s) ? ts[threadIdx.x - s] : 0;
        __syncthreads();
        ts[threadIdx.x] += t;
        __syncthreads();
    }
    if (i < SCAN_N) {
        int excl = ts[threadIdx.x] - v + g_bsum[blockIdx.x];
        g_off[i] = excl;
        g_cursor[i] = excl;
    }
}

// fill: CSR edge-source list
__global__ void fill_kernel(const int* __restrict__ src,
                            const int* __restrict__ dst) {
    int i = blockIdx.x * blockDim.x + threadIdx.x;
    if (i < RREL * EDGES) {
        int r = i / EDGES;
        int pos = atomicAdd(&g_cursor[r * NNODES + dst[i]], 1);
        g_esrc[pos] = src[i];
    }
}

// ---------------------------------------------------------------------------
// Prep: cast x to fp16 (shared A operand of all 5 GEMMs)
// ---------------------------------------------------------------------------
__global__ void convert_x_kernel(const float* __restrict__ x) {
    size_t total = (size_t)NNODES * 64;
    for (size_t i = (size_t)blockIdx.x * blockDim.x + threadIdx.x; i < total;
         i += (size_t)gridDim.x * blockDim.x) {
        float4 v = reinterpret_cast<const float4*>(x)[i];
        __half2 h01 = __float22half2_rn(make_float2(v.x, v.y));
        __half2 h23 = __float22half2_rn(make_float2(v.z, v.w));
        reinterpret_cast<__half2*>(g_x_h)[2 * i]     = h01;
        reinterpret_cast<__half2*>(g_x_h)[2 * i + 1] = h23;
    }
}

__global__ void convert_w_kernel(const float* __restrict__ weight,
                                 const float* __restrict__ wself) {
    int i = blockIdx.x * blockDim.x + threadIdx.x;
    if (i >= NGEMM * 65536) return;
    int g = i >> 16;
    int n = (i >> 8) & 255;
    int k = i & 255;
    const float* src = (g == 0) ? wself : weight + (size_t)(g - 1) * 65536;
    g_w_h[i] = __float2half_rn(src[k * 256 + n]);
}

// ---------------------------------------------------------------------------
// fp16 wmma GEMM (unchanged from the 119.6us R14 version).
// ---------------------------------------------------------------------------
#define KC   32
#define LDS  40
#define TILE_ELEMS (128 * LDS)
#define NSTAGE 3

__device__ __forceinline__ uint32_t smem_u32(const void* p) {
    uint32_t a;
    asm("{ .reg .u64 t; cvta.to.shared.u64 t, %1; cvt.u32.u64 %0, t; }" : "=r"(a) : "l"(p));
    return a;
}
__device__ __forceinline__ void cpa16(uint32_t dst, const void* src) {
    asm volatile("cp.async.cg.shared.global [%0], [%1], 16;" :: "r"(dst), "l"(src));
}
__device__ __forceinline__ void cpa16_zfill(uint32_t dst, const void* src) {
    asm volatile("cp.async.cg.shared.global [%0], [%1], 16, 0;" :: "r"(dst), "l"(src));
}

__global__ void __launch_bounds__(128)
wmma_gemm_kernel() {
    extern __shared__ __half smem[];

    const int tid = threadIdx.x;
    const int wid = tid >> 5;
    const int wm  = wid & 1;
    const int wn  = wid >> 1;
    const int m0  = blockIdx.x * 128;
    const int n0  = blockIdx.y * 128;
    const int g   = blockIdx.z;

    const __half* wh = g_w_h + (size_t)g * 65536;
    const int lrow0 = tid >> 2;
    const int lc4   = tid & 3;

    auto issue_tile = [&](int t) {
        const int k0 = t * KC;
        const int stage = t % NSTAGE;
        __half* As = smem + (stage * 2 + 0) * TILE_ELEMS;
        __half* Bs = smem + (stage * 2 + 1) * TILE_ELEMS;
        #pragma unroll
        for (int p = 0; p < 4; p++) {
            int row = lrow0 + p * 32;
            int kof = k0 + lc4 * 8;
            uint32_t soff = (uint32_t)(row * LDS + lc4 * 8) * 2;
            int gm = m0 + row;
            if (gm < NNODES) {
                cpa16(smem_u32(As) + soff, g_x_h + (size_t)gm * 256 + kof);
            } else {
                cpa16_zfill(smem_u32(As) + soff, g_x_h);
            }
            int n = n0 + row;
            cpa16(smem_u32(Bs) + soff, wh + (size_t)n * 256 + kof);
        }
        asm volatile("cp.async.commit_group;" ::: "memory");
    };

    wmma::fragment<wmma::accumulator, 16, 16, 16, float> c[4][4];
    #pragma unroll
    for (int mi = 0; mi < 4; mi++)
        #pragma unroll
        for (int ni = 0; ni < 4; ni++)
            wmma::fill_fragment(c[mi][ni], 0.0f);

    issue_tile(0);
    issue_tile(1);
    __syncthreads();

    for (int t = 0; t < 8; t++) {
        if (t < 7) {
            asm volatile("cp.async.wait_group 1;" ::: "memory");
        } else {
            asm volatile("cp.async.wait_group 0;" ::: "memory");
        }
        __syncthreads();

        const int stage = t % NSTAGE;
        const __half* As = smem + (stage * 2 + 0) * TILE_ELEMS;
        const __half* Bs = smem + (stage * 2 + 1) * TILE_ELEMS;

        #pragma unroll
        for (int ks = 0; ks < 2; ks++) {
            const int kk = ks * 16;
            wmma::fragment<wmma::matrix_a, 16, 16, 16, __half, wmma::row_major> a[4];
            wmma::fragment<wmma::matrix_b, 16, 16, 16, __half, wmma::col_major> b[4];
            #pragma unroll
            for (int mi = 0; mi < 4; mi++)
                wmma::load_matrix_sync(a[mi], As + (wm * 64 + mi * 16) * LDS + kk, LDS);
            #pragma unroll
            for (int ni = 0; ni < 4; ni++)
                wmma::load_matrix_sync(b[ni], Bs + (wn * 64 + ni * 16) * LDS + kk, LDS);
            #pragma unroll
            for (int mi = 0; mi < 4; mi++)
                #pragma unroll
                for (int ni = 0; ni < 4; ni++)
                    wmma::mma_sync(c[mi][ni], a[mi], b[ni], c[mi][ni]);
        }
        if (t + 2 < 8) issue_tile(t + 2);
    }

    float* Cg = g_Hp + (size_t)g * NPAD * 256;
    #pragma unroll
    for (int mi = 0; mi < 4; mi++)
        #pragma unroll
        for (int ni = 0; ni < 4; ni++) {
            int row = m0 + wm * 64 + mi * 16;
            int col = n0 + wn * 64 + ni * 16;
            wmma::store_matrix_sync(Cg + (size_t)row * 256 + col, c[mi][ni],
                                    256, wmma::mem_row_major);
        }
}

// ---------------------------------------------------------------------------
// Gather: one warp per node. No atomics; fuses scale + bias + relu.
// out[d] = relu( Hp[0][d] + sum_r (1/deg) * sum_{e in CSR(r,d)} Hp[r+1][src_e]
//                + bias )
// Each lane owns 8 columns (2 float4). Edge loop unrolled x2 for MLP.
// ---------------------------------------------------------------------------
__global__ void gather_kernel(const float* __restrict__ bias,
                              float* __restrict__ out) {
    int gw   = (blockIdx.x * blockDim.x + threadIdx.x) >> 5;
    int lane = threadIdx.x & 31;
    if (gw >= NNODES) return;
    int d = gw;
    int co = lane * 8;

    const float4* self = reinterpret_cast<const float4*>(g_Hp + (size_t)d * 256 + co);
    float4 a0 = self[0];
    float4 a1 = self[1];

    #pragma unroll
    for (int r = 0; r < RREL; r++) {
        int idx = r * NNODES + d;
        int dg  = g_deg[idx];
        if (dg == 0) continue;
        int beg = g_off[idx];
        int end = beg + dg;
        const float* Hr = g_Hp + (size_t)(r + 1) * NPAD * 256;

        float4 s0 = make_float4(0.f, 0.f, 0.f, 0.f);
        float4 s1 = make_float4(0.f, 0.f, 0.f, 0.f);
        int e = beg;
        for (; e + 1 < end; e += 2) {
            int sa = g_esrc[e], sb = g_esrc[e + 1];
            const float4* pa = reinterpret_cast<const float4*>(Hr + (size_t)sa * 256 + co);
            const float4* pb = reinterpret_cast<const float4*>(Hr + (size_t)sb * 256 + co);
            float4 qa0 = __ldg(&pa[0]), qa1 = __ldg(&pa[1]);
            float4 qb0 = __ldg(&pb[0]), qb1 = __ldg(&pb[1]);
            s0.x += qa0.x + qb0.x; s0.y += qa0.y + qb0.y;
            s0.z += qa0.z + qb0.z; s0.w += qa0.w + qb0.w;
            s1.x += qa1.x + qb1.x; s1.y += qa1.y + qb1.y;
            s1.z += qa1.z + qb1.z; s1.w += qa1.w + qb1.w;
        }
        if (e < end) {
            int sa = g_esrc[e];
            const float4* pa = reinterpret_cast<const float4*>(Hr + (size_t)sa * 256 + co);
            float4 qa0 = __ldg(&pa[0]), qa1 = __ldg(&pa[1]);
            s0.x += qa0.x; s0.y += qa0.y; s0.z += qa0.z; s0.w += qa0.w;
            s1.x += qa1.x; s1.y += qa1.y; s1.z += qa1.z; s1.w += qa1.w;
        }
        float w = 1.0f / (float)dg;
        a0.x += w * s0.x; a0.y += w * s0.y; a0.z += w * s0.z; a0.w += w * s0.w;
        a1.x += w * s1.x; a1.y += w * s1.y; a1.z += w * s1.z; a1.w += w * s1.w;
    }

    const float4* bv = reinterpret_cast<const float4*>(bias + co);
    float4 b0 = __ldg(&bv[0]);
    float4 b1 = __ldg(&bv[1]);
    a0.x = fmaxf(a0.x + b0.x, 0.f); a0.y = fmaxf(a0.y + b0.y, 0.f);
    a0.z = fmaxf(a0.z + b0.z, 0.f); a0.w = fmaxf(a0.w + b0.w, 0.f);
    a1.x = fmaxf(a1.x + b1.x, 0.f); a1.y = fmaxf(a1.y + b1.y, 0.f);
    a1.z = fmaxf(a1.z + b1.z, 0.f); a1.w = fmaxf(a1.w + b1.w, 0.f);

    float4* o = reinterpret_cast<float4*>(out + (size_t)d * 256 + co);
    o[0] = a0;
    o[1] = a1;
}

// ---------------------------------------------------------------------------
extern "C" void kernel_launch(void* const* d_in, const int* in_sizes, int n_in,
                              void* d_out, int out_size) {
    const float* x      = (const float*)d_in[0];
    const int*   src    = (const int*)  d_in[1];
    const int*   dst    = (const int*)  d_in[2];
    const float* weight = (const float*)d_in[3];
    const float* wself  = (const float*)d_in[4];
    const float* bias   = (const float*)d_in[5];
    float* out = (float*)d_out;

    const int SMEM_BYTES = NSTAGE * 2 * TILE_ELEMS * 2;   // 61440
    cudaFuncSetAttribute(wmma_gemm_kernel,
                         cudaFuncAttributeMaxDynamicSharedMemorySize, SMEM_BYTES);

    // wmma_gemm stays at captured-profile index 3.
    convert_x_kernel<<<2048, 256>>>(x);                                   // 0
    convert_w_kernel<<<(NGEMM * 65536 + 255) / 256, 256>>>(weight, wself);// 1
    zero_deg_kernel<<<SCAN_BLOCKS, 256>>>();                              // 2
    wmma_gemm_kernel<<<dim3(391, 2, NGEMM), 128, SMEM_BYTES>>>();         // 3
    deg_kernel<<<(RREL * EDGES + 255) / 256, 256>>>(dst);                 // 4
    scan1_kernel<<<SCAN_BLOCKS, 256>>>();                                 // 5
    scan2_kernel<<<1, 1024>>>();                                          // 6
    scan3_kernel<<<SCAN_BLOCKS, 256>>>();                                 // 7
    fill_kernel<<<(RREL * EDGES + 255) / 256, 256>>>(src, dst);           // 8
    gather_kernel<<<(NNODES * 32 + 255) / 256, 256>>>(bias, out);         // 9
}

// round 16
// speedup vs baseline: 1.2297x; 1.0599x over previous
#include <cuda_runtime.h>
#include <cuda_bf16.h>
#include <cuda_fp16.h>
#include <mma.h>
#include <cstdint>

using namespace nvcuda;

#define NNODES 50000
#define NPAD   50048
#define RREL   4
#define EDGES  80000
#define NGEMM  5          // slot 0 = self-loop, 1..4 = relations
#define SCAN_N (RREL * NNODES)               // 200000
#define SCAN_BLOCKS ((SCAN_N + 255) / 256)   // 782

// ---------------------------------------------------------------------------
// Static device scratch. Device code references symbols directly (R2 lesson:
// host-shadow addresses silently read host memory via ATS on GB300).
// ---------------------------------------------------------------------------
__device__ float  g_Hacc[(size_t)NPAD * 256];          // self-loop result (fp32, 51 MB)
__device__ __half g_Hf[(size_t)RREL * NPAD * 256];     // relation results (fp16, 102 MB)
__device__ int    g_deg[SCAN_N];
__device__ int    g_off[SCAN_N];        // CSR row offsets (exclusive prefix)
__device__ int    g_cursor[SCAN_N];     // fill cursors
__device__ int    g_bsum[1024];         // block partial sums for the scan
__device__ int    g_esrc[RREL * EDGES]; // CSR edge sources
__device__ __half g_x_h[(size_t)NNODES * 256];
__device__ __half g_w_h[NGEMM * 256 * 256];            // [g][n][k] (W transposed)

// ---------------------------------------------------------------------------
// degree + CSR pipeline
// ---------------------------------------------------------------------------
__global__ void zero_deg_kernel() {
    int i = blockIdx.x * blockDim.x + threadIdx.x;
    if (i < SCAN_N) g_deg[i] = 0;
}
__global__ void deg_kernel(const int* __restrict__ dst) {
    int i = blockIdx.x * blockDim.x + threadIdx.x;
    if (i < RREL * EDGES) {
        int r = i / EDGES;
        atomicAdd(&g_deg[r * NNODES + dst[i]], 1);
    }
}

__global__ void scan1_kernel() {
    __shared__ int ts[256];
    int i = blockIdx.x * 256 + threadIdx.x;
    int v = (i < SCAN_N) ? g_deg[i] : 0;
    ts[threadIdx.x] = v;
    __syncthreads();
    for (int s = 128; s > 0; s >>= 1) {
        if (threadIdx.x < s) ts[threadIdx.x] += ts[threadIdx.x + s];
        __syncthreads();
    }
    if (threadIdx.x == 0) g_bsum[blockIdx.x] = ts[0];
}

__global__ void scan2_kernel() {
    __shared__ int ts[1024];
    int tid = threadIdx.x;
    int v = (tid < SCAN_BLOCKS) ? g_bsum[tid] : 0;
    ts[tid] = v;
    __syncthreads();
    for (int s = 1; s < 1024; s <<= 1) {
        int t = (tid >= s) ? ts[tid - s] : 0;
        __syncthreads();
        ts[tid] += t;
        __syncthreads();
    }
    if (tid < SCAN_BLOCKS) g_bsum[tid] = ts[tid] - v;   // exclusive
}

__global__ void scan3_kernel() {
    __shared__ int ts[256];
    int i = blockIdx.x * 256 + threadIdx.x;
    int v = (i < SCAN_N) ? g_deg[i] : 0;
    ts[threadIdx.x] = v;
    __syncthreads();
    for (int s = 1; s < 256; s <<= 1) {
        int t = (threadIdx.x >= s) ? ts[threadIdx.x - s] : 0;
        __syncthreads();
        ts[threadIdx.x] += t;
        __syncthreads();
    }
    if (i < SCAN_N) {
        int excl = ts[threadIdx.x] - v + g_bsum[blockIdx.x];
        g_off[i] = excl;
        g_cursor[i] = excl;
    }
}

__global__ void fill_kernel(const int* __restrict__ src,
                            const int* __restrict__ dst) {
    int i = blockIdx.x * blockDim.x + threadIdx.x;
    if (i < RREL * EDGES) {
        int r = i / EDGES;
        int pos = atomicAdd(&g_cursor[r * NNODES + dst[i]], 1);
        g_esrc[pos] = src[i];
    }
}

// ---------------------------------------------------------------------------
// Prep: cast x / W to fp16
// ---------------------------------------------------------------------------
__global__ void convert_x_kernel(const float* __restrict__ x) {
    size_t total = (size_t)NNODES * 64;
    for (size_t i = (size_t)blockIdx.x * blockDim.x + threadIdx.x; i < total;
         i += (size_t)gridDim.x * blockDim.x) {
        float4 v = reinterpret_cast<const float4*>(x)[i];
        __half2 h01 = __float22half2_rn(make_float2(v.x, v.y));
        __half2 h23 = __float22half2_rn(make_float2(v.z, v.w));
        reinterpret_cast<__half2*>(g_x_h)[2 * i]     = h01;
        reinterpret_cast<__half2*>(g_x_h)[2 * i + 1] = h23;
    }
}

__global__ void convert_w_kernel(const float* __restrict__ weight,
                                 const float* __restrict__ wself) {
    int i = blockIdx.x * blockDim.x + threadIdx.x;
    if (i >= NGEMM * 65536) return;
    int g = i >> 16;
    int n = (i >> 8) & 255;
    int k = i & 255;
    const float* src = (g == 0) ? wself : weight + (size_t)(g - 1) * 65536;
    g_w_h[i] = __float2half_rn(src[k * 256 + n]);
}

// ---------------------------------------------------------------------------
// fp16 wmma GEMM (R14 mainloop). Epilogue: g=0 -> fp32 Hacc; g>0 -> fp16 Hf
// via direct float->half accumulator-fragment conversion (no smem staging).
// ---------------------------------------------------------------------------
#define KC   32
#define LDS  40
#define TILE_ELEMS (128 * LDS)
#define NSTAGE 3

__device__ __forceinline__ uint32_t smem_u32(const void* p) {
    uint32_t a;
    asm("{ .reg .u64 t; cvta.to.shared.u64 t, %1; cvt.u32.u64 %0, t; }" : "=r"(a) : "l"(p));
    return a;
}
__device__ __forceinline__ void cpa16(uint32_t dst, const void* src) {
    asm volatile("cp.async.cg.shared.global [%0], [%1], 16;" :: "r"(dst), "l"(src));
}
__device__ __forceinline__ void cpa16_zfill(uint32_t dst, const void* src) {
    asm volatile("cp.async.cg.shared.global [%0], [%1], 16, 0;" :: "r"(dst), "l"(src));
}

__global__ void __launch_bounds__(128)
wmma_gemm_kernel() {
    extern __shared__ __half smem[];

    const int tid = threadIdx.x;
    const int wid = tid >> 5;
    const int wm  = wid & 1;
    const int wn  = wid >> 1;
    const int m0  = blockIdx.x * 128;
    const int n0  = blockIdx.y * 128;
    const int g   = blockIdx.z;

    const __half* wh = g_w_h + (size_t)g * 65536;
    const int lrow0 = tid >> 2;
    const int lc4   = tid & 3;

    auto issue_tile = [&](int t) {
        const int k0 = t * KC;
        const int stage = t % NSTAGE;
        __half* As = smem + (stage * 2 + 0) * TILE_ELEMS;
        __half* Bs = smem + (stage * 2 + 1) * TILE_ELEMS;
        #pragma unroll
        for (int p = 0; p < 4; p++) {
            int row = lrow0 + p * 32;
            int kof = k0 + lc4 * 8;
            uint32_t soff = (uint32_t)(row * LDS + lc4 * 8) * 2;
            int gm = m0 + row;
            if (gm < NNODES) {
                cpa16(smem_u32(As) + soff, g_x_h + (size_t)gm * 256 + kof);
            } else {
                cpa16_zfill(smem_u32(As) + soff, g_x_h);
            }
            int n = n0 + row;
            cpa16(smem_u32(Bs) + soff, wh + (size_t)n * 256 + kof);
        }
        asm volatile("cp.async.commit_group;" ::: "memory");
    };

    wmma::fragment<wmma::accumulator, 16, 16, 16, float> c[4][4];
    #pragma unroll
    for (int mi = 0; mi < 4; mi++)
        #pragma unroll
        for (int ni = 0; ni < 4; ni++)
            wmma::fill_fragment(c[mi][ni], 0.0f);

    issue_tile(0);
    issue_tile(1);
    __syncthreads();

    for (int t = 0; t < 8; t++) {
        if (t < 7) {
            asm volatile("cp.async.wait_group 1;" ::: "memory");
        } else {
            asm volatile("cp.async.wait_group 0;" ::: "memory");
        }
        __syncthreads();

        const int stage = t % NSTAGE;
        const __half* As = smem + (stage * 2 + 0) * TILE_ELEMS;
        const __half* Bs = smem + (stage * 2 + 1) * TILE_ELEMS;

        #pragma unroll
        for (int ks = 0; ks < 2; ks++) {
            const int kk = ks * 16;
            wmma::fragment<wmma::matrix_a, 16, 16, 16, __half, wmma::row_major> a[4];
            wmma::fragment<wmma::matrix_b, 16, 16, 16, __half, wmma::col_major> b[4];
            #pragma unroll
            for (int mi = 0; mi < 4; mi++)
                wmma::load_matrix_sync(a[mi], As + (wm * 64 + mi * 16) * LDS + kk, LDS);
            #pragma unroll
            for (int ni = 0; ni < 4; ni++)
                wmma::load_matrix_sync(b[ni], Bs + (wn * 64 + ni * 16) * LDS + kk, LDS);
            #pragma unroll
            for (int mi = 0; mi < 4; mi++)
                #pragma unroll
                for (int ni = 0; ni < 4; ni++)
                    wmma::mma_sync(c[mi][ni], a[mi], b[ni], c[mi][ni]);
        }
        if (t + 2 < 8) issue_tile(t + 2);
    }

    if (g == 0) {
        #pragma unroll
        for (int mi = 0; mi < 4; mi++)
            #pragma unroll
            for (int ni = 0; ni < 4; ni++) {
                int row = m0 + wm * 64 + mi * 16;
                int col = n0 + wn * 64 + ni * 16;
                wmma::store_matrix_sync(g_Hacc + (size_t)row * 256 + col,
                                        c[mi][ni], 256, wmma::mem_row_major);
            }
    } else {
        // Direct fp32->fp16 accumulator-fragment conversion (documented wmma
        // mixed-precision epilogue: same-shape accumulators share element map).
        __half* Hg = g_Hf + (size_t)(g - 1) * NPAD * 256;
        #pragma unroll
        for (int mi = 0; mi < 4; mi++)
            #pragma unroll
            for (int ni = 0; ni < 4; ni++) {
                wmma::fragment<wmma::accumulator, 16, 16, 16, __half> ch;
                #pragma unroll
                for (int e = 0; e < ch.num_elements; e++)
                    ch.x[e] = __float2half_rn(c[mi][ni].x[e]);
                int row = m0 + wm * 64 + mi * 16;
                int col = n0 + wn * 64 + ni * 16;
                wmma::store_matrix_sync(Hg + (size_t)row * 256 + col,
                                        ch, 256, wmma::mem_row_major);
            }
    }
}

// ---------------------------------------------------------------------------
// Gather: one warp per node, no atomics, fused scale+bias+relu.
// out[d] = relu( Hacc[d] + sum_r (1/deg)*sum_{e in CSR(r,d)} Hf[r][src_e] + bias )
// Each lane owns 8 columns: fp32 self = 2 float4; fp16 edges = 1 uint4 each.
// ---------------------------------------------------------------------------
__global__ void gather_kernel(const float* __restrict__ bias,
                              float* __restrict__ out) {
    int gw   = (blockIdx.x * blockDim.x + threadIdx.x) >> 5;
    int lane = threadIdx.x & 31;
    if (gw >= NNODES) return;
    int d = gw;
    int co = lane * 8;

    const float4* self = reinterpret_cast<const float4*>(g_Hacc + (size_t)d * 256 + co);
    float4 a0 = self[0];
    float4 a1 = self[1];

    #pragma unroll
    for (int r = 0; r < RREL; r++) {
        int idx = r * NNODES + d;
        int dg  = g_deg[idx];
        if (dg == 0) continue;
        int beg = g_off[idx];
        int end = beg + dg;
        const __half* Hr = g_Hf + (size_t)r * NPAD * 256;

        float4 s0 = make_float4(0.f, 0.f, 0.f, 0.f);
        float4 s1 = make_float4(0.f, 0.f, 0.f, 0.f);
        int e = beg;
        for (; e + 1 < end; e += 2) {
            int sa = g_esrc[e], sb = g_esrc[e + 1];
            uint4 va = __ldg(reinterpret_cast<const uint4*>(Hr + (size_t)sa * 256 + co));
            uint4 vb = __ldg(reinterpret_cast<const uint4*>(Hr + (size_t)sb * 256 + co));
            const __half2* ha = reinterpret_cast<const __half2*>(&va);
            const __half2* hb = reinterpret_cast<const __half2*>(&vb);
            float2 p0 = __half22float2(ha[0]), q0 = __half22float2(hb[0]);
            float2 p1 = __half22float2(ha[1]), q1 = __half22float2(hb[1]);
            float2 p2 = __half22float2(ha[2]), q2 = __half22float2(hb[2]);
            float2 p3 = __half22float2(ha[3]), q3 = __half22float2(hb[3]);
            s0.x += p0.x + q0.x; s0.y += p0.y + q0.y;
            s0.z += p1.x + q1.x; s0.w += p1.y + q1.y;
            s1.x += p2.x + q2.x; s1.y += p2.y + q2.y;
            s1.z += p3.x + q3.x; s1.w += p3.y + q3.y;
        }
        if (e < end) {
            int sa = g_esrc[e];
            uint4 va = __ldg(reinterpret_cast<const uint4*>(Hr + (size_t)sa * 256 + co));
            const __half2* ha = reinterpret_cast<const __half2*>(&va);
            float2 p0 = __half22float2(ha[0]);
            float2 p1 = __half22float2(ha[1]);
            float2 p2 = __half22float2(ha[2]);
            float2 p3 = __half22float2(ha[3]);
            s0.x += p0.x; s0.y += p0.y; s0.z += p1.x; s0.w += p1.y;
            s1.x += p2.x; s1.y += p2.y; s1.z += p3.x; s1.w += p3.y;
        }
        float w = 1.0f / (float)dg;
        a0.x += w * s0.x; a0.y += w * s0.y; a0.z += w * s0.z; a0.w += w * s0.w;
        a1.x += w * s1.x; a1.y += w * s1.y; a1.z += w * s1.z; a1.w += w * s1.w;
    }

    const float4* bv = reinterpret_cast<const float4*>(bias + co);
    float4 b0 = __ldg(&bv[0]);
    float4 b1 = __ldg(&bv[1]);
    a0.x = fmaxf(a0.x + b0.x, 0.f); a0.y = fmaxf(a0.y + b0.y, 0.f);
    a0.z = fmaxf(a0.z + b0.z, 0.f); a0.w = fmaxf(a0.w + b0.w, 0.f);
    a1.x = fmaxf(a1.x + b1.x, 0.f); a1.y = fmaxf(a1.y + b1.y, 0.f);
    a1.z = fmaxf(a1.z + b1.z, 0.f); a1.w = fmaxf(a1.w + b1.w, 0.f);

    float4* o = reinterpret_cast<float4*>(out + (size_t)d * 256 + co);
    o[0] = a0;
    o[1] = a1;
}

// ---------------------------------------------------------------------------
extern "C" void kernel_launch(void* const* d_in, const int* in_sizes, int n_in,
                              void* d_out, int out_size) {
    const float* x      = (const float*)d_in[0];
    const int*   src    = (const int*)  d_in[1];
    const int*   dst    = (const int*)  d_in[2];
    const float* weight = (const float*)d_in[3];
    const float* wself  = (const float*)d_in[4];
    const float* bias   = (const float*)d_in[5];
    float* out = (float*)d_out;

    const int SMEM_BYTES = NSTAGE * 2 * TILE_ELEMS * 2;   // 61440
    cudaFuncSetAttribute(wmma_gemm_kernel,
                         cudaFuncAttributeMaxDynamicSharedMemorySize, SMEM_BYTES);

    // wmma_gemm stays at captured-profile index 3.
    convert_x_kernel<<<2048, 256>>>(x);                                   // 0
    convert_w_kernel<<<(NGEMM * 65536 + 255) / 256, 256>>>(weight, wself);// 1
    zero_deg_kernel<<<SCAN_BLOCKS, 256>>>();                              // 2
    wmma_gemm_kernel<<<dim3(391, 2, NGEMM), 128, SMEM_BYTES>>>();         // 3
    deg_kernel<<<(RREL * EDGES + 255) / 256, 256>>>(dst);                 // 4
    scan1_kernel<<<SCAN_BLOCKS, 256>>>();                                 // 5
    scan2_kernel<<<1, 1024>>>();                                          // 6
    scan3_kernel<<<SCAN_BLOCKS, 256>>>();                                 // 7
    fill_kernel<<<(RREL * EDGES + 255) / 256, 256>>>(src, dst);           // 8
    gather_kernel<<<(NNODES * 32 + 255) / 256, 256>>>(bias, out);         // 9
}

// round 17
// speedup vs baseline: 1.3794x; 1.1217x over previous
#include <cuda_runtime.h>
#include <cuda_bf16.h>
#include <cuda_fp16.h>
#include <mma.h>
#include <cstdint>

using namespace nvcuda;

#define NNODES 50000
#define RREL   4
#define EDGES  80000
#define KTOT   1280                          // 256 self + 4*256 relations
#define SCAN_N (RREL * NNODES)               // 200000
#define SCAN_BLOCKS ((SCAN_N + 255) / 256)   // 782

// ---------------------------------------------------------------------------
// Static device scratch. Device code references symbols directly (R2 lesson:
// host-shadow addresses silently read host memory via ATS on GB300).
// ---------------------------------------------------------------------------
__device__ __half g_A[(size_t)NNODES * KTOT];   // stacked A = [x | agg1..agg4], 128 MB
__device__ __half g_x_h[(size_t)NNODES * 256];  // compact fp16 x (25.6 MB, L2-resident)
__device__ __half g_w_h[256 * KTOT];            // stacked B [n][k'] (0.64 MB)
__device__ float  g_tail[128 * 256];            // tail-block staging (bias+relu applied)
__device__ int    g_deg[SCAN_N];
__device__ int    g_off[SCAN_N];
__device__ int    g_cursor[SCAN_N];
__device__ int    g_bsum[1024];
__device__ int    g_esrc[RREL * EDGES];

// ---------------------------------------------------------------------------
// degree + CSR pipeline
// ---------------------------------------------------------------------------
__global__ void zero_deg_kernel() {
    int i = blockIdx.x * blockDim.x + threadIdx.x;
    if (i < SCAN_N) g_deg[i] = 0;
}
__global__ void deg_kernel(const int* __restrict__ dst) {
    int i = blockIdx.x * blockDim.x + threadIdx.x;
    if (i < RREL * EDGES) {
        int r = i / EDGES;
        atomicAdd(&g_deg[r * NNODES + dst[i]], 1);
    }
}
__global__ void scan1_kernel() {
    __shared__ int ts[256];
    int i = blockIdx.x * 256 + threadIdx.x;
    int v = (i < SCAN_N) ? g_deg[i] : 0;
    ts[threadIdx.x] = v;
    __syncthreads();
    for (int s = 128; s > 0; s >>= 1) {
        if (threadIdx.x < s) ts[threadIdx.x] += ts[threadIdx.x + s];
        __syncthreads();
    }
    if (threadIdx.x == 0) g_bsum[blockIdx.x] = ts[0];
}
__global__ void scan2_kernel() {
    __shared__ int ts[1024];
    int tid = threadIdx.x;
    int v = (tid < SCAN_BLOCKS) ? g_bsum[tid] : 0;
    ts[tid] = v;
    __syncthreads();
    for (int s = 1; s < 1024; s <<= 1) {
        int t = (tid >= s) ? ts[tid - s] : 0;
        __syncthreads();
        ts[tid] += t;
        __syncthreads();
    }
    if (tid < SCAN_BLOCKS) g_bsum[tid] = ts[tid] - v;   // exclusive
}
__global__ void scan3_kernel() {
    __shared__ int ts[256];
    int i = blockIdx.x * 256 + threadIdx.x;
    int v = (i < SCAN_N) ? g_deg[i] : 0;
    ts[threadIdx.x] = v;
    __syncthreads();
    for (int s = 1; s < 256; s <<= 1) {
        int t = (threadIdx.x >= s) ? ts[threadIdx.x - s] : 0;
        __syncthreads();
        ts[threadIdx.x] += t;
        __syncthreads();
    }
    if (i < SCAN_N) {
        int excl = ts[threadIdx.x] - v + g_bsum[blockIdx.x];
        g_off[i] = excl;
        g_cursor[i] = excl;
    }
}
__global__ void fill_kernel(const int* __restrict__ src,
                            const int* __restrict__ dst) {
    int i = blockIdx.x * blockDim.x + threadIdx.x;
    if (i < RREL * EDGES) {
        int r = i / EDGES;
        int pos = atomicAdd(&g_cursor[r * NNODES + dst[i]], 1);
        g_esrc[pos] = src[i];
    }
}

// ---------------------------------------------------------------------------
// Prep: cast x to compact fp16
// ---------------------------------------------------------------------------
__global__ void convert_x_kernel(const float* __restrict__ x) {
    size_t total = (size_t)NNODES * 64;
    for (size_t i = (size_t)blockIdx.x * blockDim.x + threadIdx.x; i < total;
         i += (size_t)gridDim.x * blockDim.x) {
        float4 v = reinterpret_cast<const float4*>(x)[i];
        __half2 h01 = __float22half2_rn(make_float2(v.x, v.y));
        __half2 h23 = __float22half2_rn(make_float2(v.z, v.w));
        reinterpret_cast<__half2*>(g_x_h)[2 * i]     = h01;
        reinterpret_cast<__half2*>(g_x_h)[2 * i + 1] = h23;
    }
}

// Prep: stacked transposed B: g_w_h[n][k'] ; k'<256 -> wself, else W_{r}[k][n]
__global__ void convert_w_kernel(const float* __restrict__ weight,
                                 const float* __restrict__ wself) {
    int i = blockIdx.x * blockDim.x + threadIdx.x;
    if (i >= 256 * KTOT) return;
    int n  = i / KTOT;
    int kp = i % KTOT;
    float v;
    if (kp < 256) v = wself[kp * 256 + n];
    else {
        int r = (kp >> 8) - 1;
        int k = kp & 255;
        v = weight[((size_t)r * 256 + k) * 256 + n];
    }
    g_w_h[i] = __float2half_rn(v);
}

// ---------------------------------------------------------------------------
// Pre-gather: one warp per node d. Builds the stacked A row:
//   g_A[d][0:256]           = x_h[d]
//   g_A[d][256+256r : +256] = (1/deg) * sum_{e in CSR(r,d)} x_h[src_e]  (fp16)
// x_h is 25.6 MB -> L2-resident; no atomics.
// ---------------------------------------------------------------------------
__global__ void pregather_kernel() {
    int gw   = (blockIdx.x * blockDim.x + threadIdx.x) >> 5;
    int lane = threadIdx.x & 31;
    if (gw >= NNODES) return;
    int d = gw;
    int co = lane * 8;                       // 8 halves per lane

    // copy self columns
    uint4 xs = *reinterpret_cast<const uint4*>(g_x_h + (size_t)d * 256 + co);
    *reinterpret_cast<uint4*>(g_A + (size_t)d * KTOT + co) = xs;

    #pragma unroll
    for (int r = 0; r < RREL; r++) {
        int idx = r * NNODES + d;
        int dg  = g_deg[idx];
        float4 s0 = make_float4(0.f, 0.f, 0.f, 0.f);
        float4 s1 = make_float4(0.f, 0.f, 0.f, 0.f);
        if (dg > 0) {
            int beg = g_off[idx];
            int end = beg + dg;
            for (int e = beg; e < end; e++) {
                int sa = g_esrc[e];
                uint4 va = __ldg(reinterpret_cast<const uint4*>(
                                     g_x_h + (size_t)sa * 256 + co));
                const __half2* ha = reinterpret_cast<const __half2*>(&va);
                float2 p0 = __half22float2(ha[0]);
                float2 p1 = __half22float2(ha[1]);
                float2 p2 = __half22float2(ha[2]);
                float2 p3 = __half22float2(ha[3]);
                s0.x += p0.x; s0.y += p0.y; s0.z += p1.x; s0.w += p1.y;
                s1.x += p2.x; s1.y += p2.y; s1.z += p3.x; s1.w += p3.y;
            }
            float w = 1.0f / (float)dg;
            s0.x *= w; s0.y *= w; s0.z *= w; s0.w *= w;
            s1.x *= w; s1.y *= w; s1.z *= w; s1.w *= w;
        }
        uint4 o;
        __half2* op = reinterpret_cast<__half2*>(&o);
        op[0] = __float22half2_rn(make_float2(s0.x, s0.y));
        op[1] = __float22half2_rn(make_float2(s0.z, s0.w));
        op[2] = __float22half2_rn(make_float2(s1.x, s1.y));
        op[3] = __float22half2_rn(make_float2(s1.z, s1.w));
        *reinterpret_cast<uint4*>(g_A + (size_t)d * KTOT + 256 + r * 256 + co) = o;
    }
}

// ---------------------------------------------------------------------------
// fp16 wmma GEMM over K=1280, fused bias (accumulator init) + relu.
// out[m0:m0+128, n0:n0+128] = relu([x|agg] @ Wstack + bias)
// grid (391, 2), 128 threads, warp tile 64x64, KC=32, 3-stage cp.async.
// Tail block (m0=49920) stores to g_tail; copy_tail_kernel finishes it.
// ---------------------------------------------------------------------------
#define KC   32
#define LDS  40
#define TILE_ELEMS (128 * LDS)               // 5120 halves per matrix tile
#define NSTAGE 3
#define NCHUNK (KTOT / KC)                   // 40
#define SMEM_PIPE_BYTES (NSTAGE * 2 * TILE_ELEMS * 2)   // 61440
#define SMEM_BYTES (SMEM_PIPE_BYTES + 16 * 128 * 4)     // + bias tile = 69632

__device__ __forceinline__ uint32_t smem_u32(const void* p) {
    uint32_t a;
    asm("{ .reg .u64 t; cvta.to.shared.u64 t, %1; cvt.u32.u64 %0, t; }" : "=r"(a) : "l"(p));
    return a;
}
__device__ __forceinline__ void cpa16(uint32_t dst, const void* src) {
    asm volatile("cp.async.cg.shared.global [%0], [%1], 16;" :: "r"(dst), "l"(src));
}
__device__ __forceinline__ void cpa16_zfill(uint32_t dst, const void* src) {
    asm volatile("cp.async.cg.shared.global [%0], [%1], 16, 0;" :: "r"(dst), "l"(src));
}

__global__ void __launch_bounds__(128)
wmma_gemm_kernel(const float* __restrict__ bias, float* __restrict__ out) {
    extern __shared__ char smraw[];
    __half* smem   = reinterpret_cast<__half*>(smraw);
    float*  bias_s = reinterpret_cast<float*>(smraw + SMEM_PIPE_BYTES);  // [16][128]

    const int tid = threadIdx.x;
    const int wid = tid >> 5;
    const int wm  = wid & 1;
    const int wn  = wid >> 1;
    const int m0  = blockIdx.x * 128;
    const int n0  = blockIdx.y * 128;

    const int lrow0 = tid >> 2;
    const int lc4   = tid & 3;

    auto issue_tile = [&](int t) {
        const int k0 = t * KC;
        const int stage = t % NSTAGE;
        __half* As = smem + (stage * 2 + 0) * TILE_ELEMS;
        __half* Bs = smem + (stage * 2 + 1) * TILE_ELEMS;
        #pragma unroll
        for (int p = 0; p < 4; p++) {
            int row = lrow0 + p * 32;
            int kof = k0 + lc4 * 8;
            uint32_t soff = (uint32_t)(row * LDS + lc4 * 8) * 2;
            int gm = m0 + row;
            if (gm < NNODES) {
                cpa16(smem_u32(As) + soff, g_A + (size_t)gm * KTOT + kof);
            } else {
                cpa16_zfill(smem_u32(As) + soff, g_A);
            }
            int n = n0 + row;
            cpa16(smem_u32(Bs) + soff, g_w_h + (size_t)n * KTOT + kof);
        }
        asm volatile("cp.async.commit_group;" ::: "memory");
    };

    // fill bias tile: 16 identical rows of bias[n0 .. n0+128)
    #pragma unroll
    for (int q = 0; q < 16; q++) {
        int e = tid + q * 128;                 // 0..2047
        int row = e >> 7, col = e & 127;
        bias_s[row * 128 + col] = __ldg(&bias[n0 + col]);
    }

    issue_tile(0);
    issue_tile(1);
    __syncthreads();   // bias tile ready + pipeline prologue barrier

    // init accumulators from the bias tile (every 16x16 tile sees bias rows)
    wmma::fragment<wmma::accumulator, 16, 16, 16, float> c[4][4];
    #pragma unroll
    for (int mi = 0; mi < 4; mi++)
        #pragma unroll
        for (int ni = 0; ni < 4; ni++)
            wmma::load_matrix_sync(c[mi][ni], bias_s + wn * 64 + ni * 16,
                                   128, wmma::mem_row_major);

    for (int t = 0; t < NCHUNK; t++) {
        if (t < NCHUNK - 1) {
            asm volatile("cp.async.wait_group 1;" ::: "memory");
        } else {
            asm volatile("cp.async.wait_group 0;" ::: "memory");
        }
        __syncthreads();

        const int stage = t % NSTAGE;
        const __half* As = smem + (stage * 2 + 0) * TILE_ELEMS;
        const __half* Bs = smem + (stage * 2 + 1) * TILE_ELEMS;

        #pragma unroll
        for (int ks = 0; ks < 2; ks++) {
            const int kk = ks * 16;
            wmma::fragment<wmma::matrix_a, 16, 16, 16, __half, wmma::row_major> a[4];
            wmma::fragment<wmma::matrix_b, 16, 16, 16, __half, wmma::col_major> b[4];
            #pragma unroll
            for (int mi = 0; mi < 4; mi++)
                wmma::load_matrix_sync(a[mi], As + (wm * 64 + mi * 16) * LDS + kk, LDS);
            #pragma unroll
            for (int ni = 0; ni < 4; ni++)
                wmma::load_matrix_sync(b[ni], Bs + (wn * 64 + ni * 16) * LDS + kk, LDS);
            #pragma unroll
            for (int mi = 0; mi < 4; mi++)
                #pragma unroll
                for (int ni = 0; ni < 4; ni++)
                    wmma::mma_sync(c[mi][ni], a[mi], b[ni], c[mi][ni]);
        }
        if (t + 2 < NCHUNK) issue_tile(t + 2);
    }

    // relu (elementwise on fragments: mapping-independent) + store
    const bool tail = (m0 + 128 > NNODES);
    #pragma unroll
    for (int mi = 0; mi < 4; mi++)
        #pragma unroll
        for (int ni = 0; ni < 4; ni++) {
            #pragma unroll
            for (int e = 0; e < c[mi][ni].num_elements; e++)
                c[mi][ni].x[e] = fmaxf(c[mi][ni].x[e], 0.0f);
            int lrow = wm * 64 + mi * 16;
            int col  = n0 + wn * 64 + ni * 16;
            if (!tail) {
                wmma::store_matrix_sync(out + (size_t)(m0 + lrow) * 256 + col,
                                        c[mi][ni], 256, wmma::mem_row_major);
            } else {
                wmma::store_matrix_sync(g_tail + (size_t)lrow * 256 + col,
                                        c[mi][ni], 256, wmma::mem_row_major);
            }
        }
}

// copy valid tail rows (49920..49999) from staging into out
__global__ void copy_tail_kernel(float* __restrict__ out) {
    int i = blockIdx.x * blockDim.x + threadIdx.x;   // over 80*64 float4
    if (i < 80 * 64) {
        reinterpret_cast<float4*>(out + (size_t)49920 * 256)[i] =
            reinterpret_cast<const float4*>(g_tail)[i];
    }
}

// ---------------------------------------------------------------------------
extern "C" void kernel_launch(void* const* d_in, const int* in_sizes, int n_in,
                              void* d_out, int out_size) {
    const float* x      = (const float*)d_in[0];
    const int*   src    = (const int*)  d_in[1];
    const int*   dst    = (const int*)  d_in[2];
    const float* weight = (const float*)d_in[3];
    const float* wself  = (const float*)d_in[4];
    const float* bias   = (const float*)d_in[5];
    float* out = (float*)d_out;

    cudaFuncSetAttribute(wmma_gemm_kernel,
                         cudaFuncAttributeMaxDynamicSharedMemorySize, SMEM_BYTES);

    convert_x_kernel<<<2048, 256>>>(x);                                   // 0
    zero_deg_kernel<<<SCAN_BLOCKS, 256>>>();                              // 1
    deg_kernel<<<(RREL * EDGES + 255) / 256, 256>>>(dst);                 // 2
    scan1_kernel<<<SCAN_BLOCKS, 256>>>();                                 // 3
    scan2_kernel<<<1, 1024>>>();                                          // 4
    scan3_kernel<<<SCAN_BLOCKS, 256>>>();                                 // 5
    fill_kernel<<<(RREL * EDGES + 255) / 256, 256>>>(src, dst);           // 6
    convert_w_kernel<<<(256 * KTOT + 255) / 256, 256>>>(weight, wself);   // 7
    pregather_kernel<<<(NNODES * 32 + 255) / 256, 256>>>();               // 8
    wmma_gemm_kernel<<<dim3(391, 2), 128, SMEM_BYTES>>>(bias, out);       // 9
    copy_tail_kernel<<<(80 * 64 + 255) / 256, 256>>>(out);                // 10
}